// round 5
// baseline (speedup 1.0000x reference)
#include <cuda_runtime.h>
#include <cstdint>
#include <cstddef>

#define TT   2048
#define BB   64
#define SS   256
#define INK  64
#define DK   32
#define WK   (INK + DK)      // 96
#define CCH  64              // chunks
#define LCH  32              // chunk length (TT/CCH)
#define BT   32              // batch tile for pass1/pass3
#define NBT  (BB / BT)       // 2
#define TBS  (TT * BB * SS)  // 33,554,432
#define PAD  36              // smem row stride (floats), 144B

// ---------------- device scratch ----------------
__device__ float g_At[SS * SS];            // At[k][s] = A[s][k]
__device__ float g_Wt[WK * SS];            // Wt[i][s] = packed [Bw^T ; Ew^T]
__device__ float g_PA[SS * SS];            // power ping
__device__ float g_PB[SS * SS];            // power pong
__device__ float g_drive[TBS];             // drive[t,b,s]
__device__ float g_localEnd[(CCH - 1) * BB * SS];
__device__ float g_xstart[CCH * BB * SS];
__device__ unsigned g_sync;

// ---------------- packed f32x2 helpers ----------------
__device__ __forceinline__ void fma2(unsigned long long& acc,
                                     unsigned long long a, unsigned long long b) {
    asm("fma.rn.f32x2 %0, %1, %2, %0;" : "+l"(acc) : "l"(a), "l"(b));
}
__device__ __forceinline__ void add2(unsigned long long& acc, unsigned long long a) {
    asm("add.rn.f32x2 %0, %1, %0;" : "+l"(acc) : "l"(a));
}
__device__ __forceinline__ unsigned long long pack2(float lo, float hi) {
    unsigned long long r;
    asm("mov.b64 %0, {%1, %2};" : "=l"(r) : "f"(lo), "f"(hi));
    return r;
}
__device__ __forceinline__ float2 unpack2(unsigned long long v) {
    float2 f;
    asm("mov.b64 {%0, %1}, %2;" : "=f"(f.x), "=f"(f.y) : "l"(v));
    return f;
}

// ---------------- prep ----------------
__global__ void __launch_bounds__(256) k_prep(const float* __restrict__ A,
                                              const float* __restrict__ Bw,
                                              const float* __restrict__ Ew) {
    int idx = blockIdx.x * blockDim.x + threadIdx.x;
    if (idx == 0) g_sync = 0u;
    if (idx < SS * SS) {
        int k = idx / SS, s = idx % SS;
        g_At[idx] = A[s * SS + k];
    } else {
        int j = idx - SS * SS;
        if (j < WK * SS) {
            int i = j / SS, s = j % SS;
            g_Wt[j] = (i < INK) ? Bw[s * INK + i] : Ew[s * DK + (i - INK)];
        }
    }
}

// ======== GEMM core (half-split): 16 rows x 2 cols per thread ========
// sx[k][PAD] state; roff = h*16; wbase = weights + s0 (LDG.64 per k).
// acc0[j]/acc1[j] (j=0..7) hold rows (roff+2j, roff+2j+1) for cols s0/s0+1.
template <int KTILES>
__device__ __forceinline__ void gemm_half(const float (*sx)[PAD], int roff,
                                          const float* wbase,
                                          unsigned long long acc0[8],
                                          unsigned long long acc1[8]) {
    float2 wv[8];
#pragma unroll
    for (int i = 0; i < 8; ++i) wv[i] = *(const float2*)(wbase + (size_t)i * SS);

#pragma unroll 1
    for (int kt = 0; kt < KTILES; ++kt) {
        float2 wn[8];
        if (kt < KTILES - 1) {
#pragma unroll
            for (int i = 0; i < 8; ++i)
                wn[i] = *(const float2*)(wbase + (size_t)((kt + 1) * 8 + i) * SS);
        }
#pragma unroll
        for (int i = 0; i < 8; ++i) {
            const int k = kt * 8 + i;
            unsigned long long w0 = pack2(wv[i].x, wv[i].x);
            unsigned long long w1 = pack2(wv[i].y, wv[i].y);
            const ulonglong2* xv = (const ulonglong2*)(&sx[k][roff]);
#pragma unroll
            for (int q = 0; q < 4; ++q) {
                ulonglong2 v = xv[q];
                fma2(acc0[2 * q],     v.x, w0);
                fma2(acc0[2 * q + 1], v.y, w0);
                fma2(acc1[2 * q],     v.x, w1);
                fma2(acc1[2 * q + 1], v.y, w1);
            }
        }
#pragma unroll
        for (int i = 0; i < 8; ++i) wv[i] = wn[i];
    }
}

// ---------------- drive ----------------
__global__ void __launch_bounds__(256) k_drive(const float* __restrict__ U,
                                               const float* __restrict__ D) {
    __shared__ __align__(16) float sRow[WK][PAD];
    const int R0   = blockIdx.x * 32;
    const int tid  = threadIdx.x;
    const int h    = tid >> 7;
    const int lane = tid & 127;
    const int s0   = 2 * lane;
    const int roff = h * 16;

    for (int e = tid; e < 32 * WK; e += 256) {
        int r = e / WK, i = e % WK;
        size_t R = (size_t)(R0 + r);
        sRow[i][r] = (i < INK) ? U[R * INK + i] : D[R * DK + (i - INK)];
    }
    __syncthreads();

    unsigned long long acc0[8], acc1[8];
#pragma unroll
    for (int p = 0; p < 8; ++p) { acc0[p] = 0ull; acc1[p] = 0ull; }

    gemm_half<WK / 8>(sRow, roff, g_Wt + s0, acc0, acc1);

#pragma unroll
    for (int j = 0; j < 8; ++j) {
        float2 f0 = unpack2(acc0[j]);
        float2 f1 = unpack2(acc1[j]);
        *(float2*)(&g_drive[(size_t)(R0 + roff + 2 * j) * SS + s0])     = make_float2(f0.x, f1.x);
        *(float2*)(&g_drive[(size_t)(R0 + roff + 2 * j + 1) * SS + s0]) = make_float2(f0.y, f1.y);
    }
}

// ---------------- powers: (A^T)^32 via 5 fused squarings ----------------
__global__ void __launch_bounds__(256) k_powers() {
    __shared__ float sRow[2][SS];
    const int tid = threadIdx.x;
    const int k0  = blockIdx.x * 2;

    const float* src = g_At;
    float*       dst = g_PA;
#pragma unroll 1
    for (int step = 0; step < 5; ++step) {
        sRow[0][tid] = src[(size_t)k0 * SS + tid];
        sRow[1][tid] = src[(size_t)(k0 + 1) * SS + tid];
        __syncthreads();
        float a0 = 0.f, a1 = 0.f;
#pragma unroll 4
        for (int j = 0; j < SS; ++j) {
            float b = src[(size_t)j * SS + tid];
            a0 = fmaf(sRow[0][j], b, a0);
            a1 = fmaf(sRow[1][j], b, a1);
        }
        dst[(size_t)k0 * SS + tid]       = a0;
        dst[(size_t)(k0 + 1) * SS + tid] = a1;
        __syncthreads();
        if (tid == 0) {
            __threadfence();
            atomicAdd(&g_sync, 1u);
            unsigned target = 128u * (unsigned)(step + 1);
            while (*((volatile unsigned*)&g_sync) < target) { __nanosleep(64); }
        }
        __syncthreads();
        src = dst;
        dst = (dst == g_PA) ? g_PB : g_PA;
    }
}

// ---------------- pass1 ----------------
__global__ void __launch_bounds__(256) k_pass1() {
    const int c    = blockIdx.x / NBT;
    const int b0   = (blockIdx.x % NBT) * BT;
    const int tid  = threadIdx.x;
    const int h    = tid >> 7;
    const int lane = tid & 127;
    const int s0   = 2 * lane;
    const int roff = h * 16;
    __shared__ __align__(16) float sx[2][SS][PAD];

    // j = 0: x1 = drive[t0]
    {
        const int t0 = c * LCH;
#pragma unroll
        for (int r = 0; r < 16; ++r) {
            float2 d = *(const float2*)(&g_drive[((size_t)t0 * BB + b0 + roff + r) * SS + s0]);
            sx[0][s0][roff + r]     = d.x;
            sx[0][s0 + 1][roff + r] = d.y;
        }
    }
    __syncthreads();

    int pb = 0;
#pragma unroll 1
    for (int j = 1; j < LCH; ++j) {
        const int t = c * LCH + j;
        unsigned long long acc0[8], acc1[8];
#pragma unroll
        for (int p = 0; p < 8; ++p) { acc0[p] = 0ull; acc1[p] = 0ull; }

        gemm_half<SS / 8>(sx[pb], roff, g_At + s0, acc0, acc1);

        const float* dr = g_drive + ((size_t)t * BB + b0 + roff) * SS + s0;
#pragma unroll
        for (int q = 0; q < 8; ++q) {
            float2 da = *(const float2*)(dr + (size_t)(2 * q) * SS);
            float2 db = *(const float2*)(dr + (size_t)(2 * q + 1) * SS);
            add2(acc0[q], pack2(da.x, db.x));
            add2(acc1[q], pack2(da.y, db.y));
        }

        ulonglong2* q0 = (ulonglong2*)(&sx[1 - pb][s0][roff]);
        ulonglong2* q1 = (ulonglong2*)(&sx[1 - pb][s0 + 1][roff]);
#pragma unroll
        for (int q = 0; q < 4; ++q) {
            q0[q] = make_ulonglong2(acc0[2 * q], acc0[2 * q + 1]);
            q1[q] = make_ulonglong2(acc1[2 * q], acc1[2 * q + 1]);
        }
        __syncthreads();
        pb = 1 - pb;
    }
#pragma unroll
    for (int r = 0; r < 16; ++r)
        *(float2*)(&g_localEnd[((size_t)c * BB + b0 + roff + r) * SS + s0]) =
            make_float2(sx[pb][s0][roff + r], sx[pb][s0 + 1][roff + r]);
}

// ---------------- pass2: boundary recurrence, 128 thr x 2 cols, 2 rows/CTA ----------------
__global__ void __launch_bounds__(128) k_pass2(const float* __restrict__ x0) {
    const int b0 = blockIdx.x * 2;   // 32 CTAs
    const int s0 = 2 * threadIdx.x;
    __shared__ __align__(8) float sxp[SS][2];   // [k][row]

    float2 vA = *(const float2*)(&x0[(size_t)b0 * SS + s0]);        // row b0, cols s0,s0+1
    float2 vB = *(const float2*)(&x0[(size_t)(b0 + 1) * SS + s0]);  // row b0+1
    sxp[s0][0] = vA.x;     sxp[s0][1] = vB.x;
    sxp[s0 + 1][0] = vA.y; sxp[s0 + 1][1] = vB.y;
    *(float2*)(&g_xstart[((size_t)b0) * SS + s0])       = vA;
    *(float2*)(&g_xstart[((size_t)(b0 + 1)) * SS + s0]) = vB;
    __syncthreads();

#pragma unroll 1
    for (int c = 1; c < CCH; ++c) {
        float2 eA = *(const float2*)(&g_localEnd[((size_t)(c - 1) * BB + b0) * SS + s0]);
        float2 eB = *(const float2*)(&g_localEnd[((size_t)(c - 1) * BB + b0 + 1) * SS + s0]);
        unsigned long long acc0[4], acc1[4];
#pragma unroll
        for (int u = 0; u < 4; ++u) { acc0[u] = 0ull; acc1[u] = 0ull; }
        const float* wp = g_PA + s0;   // (A^T)^32
#pragma unroll 2
        for (int k = 0; k < SS; k += 4) {
#pragma unroll
            for (int u = 0; u < 4; ++u) {
                float2 w = *(const float2*)(wp + (size_t)(k + u) * SS);
                unsigned long long xp = *(const unsigned long long*)(&sxp[k + u][0]);
                fma2(acc0[u], xp, pack2(w.x, w.x));
                fma2(acc1[u], xp, pack2(w.y, w.y));
            }
        }
        add2(acc0[0], acc0[1]); add2(acc0[2], acc0[3]); add2(acc0[0], acc0[2]);
        add2(acc1[0], acc1[1]); add2(acc1[2], acc1[3]); add2(acc1[0], acc1[2]);
        float2 f0 = unpack2(acc0[0]);   // col s0: (row b0, row b0+1)
        float2 f1 = unpack2(acc1[0]);   // col s0+1
        f0.x += eA.x; f0.y += eB.x;
        f1.x += eA.y; f1.y += eB.y;
        __syncthreads();
        sxp[s0][0] = f0.x;     sxp[s0][1] = f0.y;
        sxp[s0 + 1][0] = f1.x; sxp[s0 + 1][1] = f1.y;
        __syncthreads();
        *(float2*)(&g_xstart[((size_t)c * BB + b0) * SS + s0])     = make_float2(f0.x, f1.x);
        *(float2*)(&g_xstart[((size_t)c * BB + b0 + 1) * SS + s0]) = make_float2(f0.y, f1.y);
    }
}

// ---------------- pass3 ----------------
__global__ void __launch_bounds__(256) k_pass3(float* __restrict__ out, int dup) {
    const int c    = blockIdx.x / NBT;
    const int b0   = (blockIdx.x % NBT) * BT;
    const int tid  = threadIdx.x;
    const int h    = tid >> 7;
    const int lane = tid & 127;
    const int s0   = 2 * lane;
    const int roff = h * 16;
    __shared__ __align__(16) float sx[2][SS][PAD];

#pragma unroll
    for (int r = 0; r < 16; ++r) {
        float2 v = *(const float2*)(&g_xstart[((size_t)c * BB + b0 + roff + r) * SS + s0]);
        sx[0][s0][roff + r]     = v.x;
        sx[0][s0 + 1][roff + r] = v.y;
    }
    __syncthreads();

    float* out2 = out + (size_t)TBS;
    int pb = 0;

#pragma unroll 1
    for (int j = 0; j < LCH; ++j) {
        const int t = c * LCH + j;
        unsigned long long acc0[8], acc1[8];
#pragma unroll
        for (int p = 0; p < 8; ++p) { acc0[p] = 0ull; acc1[p] = 0ull; }

        gemm_half<SS / 8>(sx[pb], roff, g_At + s0, acc0, acc1);

        const float* dr = g_drive + ((size_t)t * BB + b0 + roff) * SS + s0;
#pragma unroll
        for (int q = 0; q < 8; ++q) {
            float2 da = *(const float2*)(dr + (size_t)(2 * q) * SS);
            float2 db = *(const float2*)(dr + (size_t)(2 * q + 1) * SS);
            add2(acc0[q], pack2(da.x, db.x));
            add2(acc1[q], pack2(da.y, db.y));
        }

        ulonglong2* q0 = (ulonglong2*)(&sx[1 - pb][s0][roff]);
        ulonglong2* q1 = (ulonglong2*)(&sx[1 - pb][s0 + 1][roff]);
#pragma unroll
        for (int q = 0; q < 4; ++q) {
            q0[q] = make_ulonglong2(acc0[2 * q], acc0[2 * q + 1]);
            q1[q] = make_ulonglong2(acc1[2 * q], acc1[2 * q + 1]);
        }

        size_t obase = ((size_t)t * BB + b0 + roff) * SS + s0;
#pragma unroll
        for (int q = 0; q < 8; ++q) {
            float2 f0 = unpack2(acc0[q]);
            float2 f1 = unpack2(acc1[q]);
            float2 oA = make_float2(f0.x, f1.x);
            float2 oB = make_float2(f0.y, f1.y);
            size_t oa = obase + (size_t)(2 * q) * SS;
            size_t ob = obase + (size_t)(2 * q + 1) * SS;
            *(float2*)(&out[oa]) = oA;
            *(float2*)(&out[ob]) = oB;
            if (dup) {
                *(float2*)(&out2[oa]) = oA;
                *(float2*)(&out2[ob]) = oB;
            }
        }
        __syncthreads();
        pb = 1 - pb;
    }
}

// ---------------- launcher ----------------
extern "C" void kernel_launch(void* const* d_in, const int* in_sizes, int n_in,
                              void* d_out, int out_size) {
    const float* x  = (const float*)d_in[0];
    const float* U  = (const float*)d_in[1];
    const float* D  = (const float*)d_in[2];
    const float* Aw = (const float*)d_in[3];
    const float* Bw = (const float*)d_in[4];
    const float* Ew = (const float*)d_in[5];
    float* out = (float*)d_out;
    int dup = (out_size >= 2 * TBS) ? 1 : 0;

    k_prep<<<(SS * SS + WK * SS + 255) / 256, 256>>>(Aw, Bw, Ew);   // 0
    k_drive<<<(TT * BB) / 32, 256>>>(U, D);                          // 1
    k_powers<<<SS / 2, 256>>>();                                     // 2
    k_pass1<<<(CCH - 1) * NBT, 256>>>();                             // 3
    k_pass2<<<BB / 2, 128>>>(x);                                     // 4
    k_pass3<<<CCH * NBT, 256>>>(out, dup);                           // 5
}

// round 6
// speedup vs baseline: 1.1324x; 1.1324x over previous
#include <cuda_runtime.h>
#include <cstdint>
#include <cstddef>

#define TT   2048
#define BB   64
#define SS   256
#define INK  64
#define DK   32
#define WK   (INK + DK)      // 96
#define CCH  64              // chunks
#define LCH  32              // chunk length (TT/CCH)
#define BT   32              // batch tile for pass1/pass3
#define NBT  (BB / BT)       // 2
#define TBS  (TT * BB * SS)  // 33,554,432
#define PAD  36              // smem row stride (floats), 144B

// ---------------- device scratch ----------------
__device__ float g_At[SS * SS];            // At[k][s] = A[s][k]
__device__ float g_Wt[WK * SS];            // Wt[i][s] = packed [Bw^T ; Ew^T]
__device__ float g_PA[SS * SS];            // power ping
__device__ float g_PB[SS * SS];            // power pong
__device__ float g_drive[TBS];             // drive[t,b,s]
__device__ float g_localEnd[(CCH - 1) * BB * SS];
__device__ float g_xstart[CCH * BB * SS];
__device__ unsigned g_sync;

// ---------------- packed f32x2 helpers ----------------
__device__ __forceinline__ void fma2(unsigned long long& acc,
                                     unsigned long long a, unsigned long long b) {
    asm("fma.rn.f32x2 %0, %1, %2, %0;" : "+l"(acc) : "l"(a), "l"(b));
}
__device__ __forceinline__ void add2(unsigned long long& acc, unsigned long long a) {
    asm("add.rn.f32x2 %0, %1, %0;" : "+l"(acc) : "l"(a));
}
__device__ __forceinline__ unsigned long long pack2(float lo, float hi) {
    unsigned long long r;
    asm("mov.b64 %0, {%1, %2};" : "=l"(r) : "f"(lo), "f"(hi));
    return r;
}
__device__ __forceinline__ float2 unpack2(unsigned long long v) {
    float2 f;
    asm("mov.b64 {%0, %1}, %2;" : "=f"(f.x), "=f"(f.y) : "l"(v));
    return f;
}

// ---------------- prep ----------------
__global__ void __launch_bounds__(256) k_prep(const float* __restrict__ A,
                                              const float* __restrict__ Bw,
                                              const float* __restrict__ Ew) {
    int idx = blockIdx.x * blockDim.x + threadIdx.x;
    if (idx == 0) g_sync = 0u;
    if (idx < SS * SS) {
        int k = idx / SS, s = idx % SS;
        g_At[idx] = A[s * SS + k];
    } else {
        int j = idx - SS * SS;
        if (j < WK * SS) {
            int i = j / SS, s = j % SS;
            g_Wt[j] = (i < INK) ? Bw[s * INK + i] : Ew[s * DK + (i - INK)];
        }
    }
}

// ======== GEMM core (half-split): 16 rows x 2 cols per thread ========
template <int KTILES>
__device__ __forceinline__ void gemm_half(const float (*sx)[PAD], int roff,
                                          const float* wbase,
                                          unsigned long long acc0[8],
                                          unsigned long long acc1[8]) {
    float2 wv[8];
#pragma unroll
    for (int i = 0; i < 8; ++i) wv[i] = *(const float2*)(wbase + (size_t)i * SS);

#pragma unroll 1
    for (int kt = 0; kt < KTILES; ++kt) {
        float2 wn[8];
        if (kt < KTILES - 1) {
#pragma unroll
            for (int i = 0; i < 8; ++i)
                wn[i] = *(const float2*)(wbase + (size_t)((kt + 1) * 8 + i) * SS);
        }
#pragma unroll
        for (int i = 0; i < 8; ++i) {
            const int k = kt * 8 + i;
            unsigned long long w0 = pack2(wv[i].x, wv[i].x);
            unsigned long long w1 = pack2(wv[i].y, wv[i].y);
            const ulonglong2* xv = (const ulonglong2*)(&sx[k][roff]);
#pragma unroll
            for (int q = 0; q < 4; ++q) {
                ulonglong2 v = xv[q];
                fma2(acc0[2 * q],     v.x, w0);
                fma2(acc0[2 * q + 1], v.y, w0);
                fma2(acc1[2 * q],     v.x, w1);
                fma2(acc1[2 * q + 1], v.y, w1);
            }
        }
#pragma unroll
        for (int i = 0; i < 8; ++i) wv[i] = wn[i];
    }
}

// ---------------- drive ----------------
__global__ void __launch_bounds__(256) k_drive(const float* __restrict__ U,
                                               const float* __restrict__ D) {
    __shared__ __align__(16) float sRow[WK][PAD];
    const int R0   = blockIdx.x * 32;
    const int tid  = threadIdx.x;
    const int h    = tid >> 7;
    const int lane = tid & 127;
    const int s0   = 2 * lane;
    const int roff = h * 16;

    for (int e = tid; e < 32 * WK; e += 256) {
        int r = e / WK, i = e % WK;
        size_t R = (size_t)(R0 + r);
        sRow[i][r] = (i < INK) ? U[R * INK + i] : D[R * DK + (i - INK)];
    }
    __syncthreads();

    unsigned long long acc0[8], acc1[8];
#pragma unroll
    for (int p = 0; p < 8; ++p) { acc0[p] = 0ull; acc1[p] = 0ull; }

    gemm_half<WK / 8>(sRow, roff, g_Wt + s0, acc0, acc1);

#pragma unroll
    for (int j = 0; j < 8; ++j) {
        float2 f0 = unpack2(acc0[j]);
        float2 f1 = unpack2(acc1[j]);
        *(float2*)(&g_drive[(size_t)(R0 + roff + 2 * j) * SS + s0])     = make_float2(f0.x, f1.x);
        *(float2*)(&g_drive[(size_t)(R0 + roff + 2 * j + 1) * SS + s0]) = make_float2(f0.y, f1.y);
    }
}

// ---------------- powers: (A^T)^32 via 5 fused squarings ----------------
__global__ void __launch_bounds__(256) k_powers() {
    __shared__ float sRow[2][SS];
    const int tid = threadIdx.x;
    const int k0  = blockIdx.x * 2;

    const float* src = g_At;
    float*       dst = g_PA;
#pragma unroll 1
    for (int step = 0; step < 5; ++step) {
        sRow[0][tid] = src[(size_t)k0 * SS + tid];
        sRow[1][tid] = src[(size_t)(k0 + 1) * SS + tid];
        __syncthreads();
        float a0 = 0.f, a1 = 0.f;
#pragma unroll 4
        for (int j = 0; j < SS; ++j) {
            float b = src[(size_t)j * SS + tid];
            a0 = fmaf(sRow[0][j], b, a0);
            a1 = fmaf(sRow[1][j], b, a1);
        }
        dst[(size_t)k0 * SS + tid]       = a0;
        dst[(size_t)(k0 + 1) * SS + tid] = a1;
        __syncthreads();
        if (tid == 0) {
            __threadfence();
            atomicAdd(&g_sync, 1u);
            unsigned target = 128u * (unsigned)(step + 1);
            while (*((volatile unsigned*)&g_sync) < target) { __nanosleep(64); }
        }
        __syncthreads();
        src = dst;
        dst = (dst == g_PA) ? g_PB : g_PA;
    }
}

// ---------------- pass1 ----------------
__global__ void __launch_bounds__(256) k_pass1() {
    const int c    = blockIdx.x / NBT;
    const int b0   = (blockIdx.x % NBT) * BT;
    const int tid  = threadIdx.x;
    const int h    = tid >> 7;
    const int lane = tid & 127;
    const int s0   = 2 * lane;
    const int roff = h * 16;
    __shared__ __align__(16) float sx[2][SS][PAD];

    // j = 0: x1 = drive[t0]
    {
        const int t0 = c * LCH;
#pragma unroll
        for (int r = 0; r < 16; ++r) {
            float2 d = *(const float2*)(&g_drive[((size_t)t0 * BB + b0 + roff + r) * SS + s0]);
            sx[0][s0][roff + r]     = d.x;
            sx[0][s0 + 1][roff + r] = d.y;
        }
    }
    __syncthreads();

    int pb = 0;
#pragma unroll 1
    for (int j = 1; j < LCH; ++j) {
        const int t = c * LCH + j;

        // PREFETCH drive for this step BEFORE the gemm: LDGs stay in flight
        // for the entire k-loop, keeping DRAM latency off the critical path.
        const float* dr = g_drive + ((size_t)t * BB + b0 + roff) * SS + s0;
        float2 da[8], db[8];
#pragma unroll
        for (int q = 0; q < 8; ++q) {
            da[q] = *(const float2*)(dr + (size_t)(2 * q) * SS);
            db[q] = *(const float2*)(dr + (size_t)(2 * q + 1) * SS);
        }

        unsigned long long acc0[8], acc1[8];
#pragma unroll
        for (int p = 0; p < 8; ++p) { acc0[p] = 0ull; acc1[p] = 0ull; }

        gemm_half<SS / 8>(sx[pb], roff, g_At + s0, acc0, acc1);

#pragma unroll
        for (int q = 0; q < 8; ++q) {
            add2(acc0[q], pack2(da[q].x, db[q].x));
            add2(acc1[q], pack2(da[q].y, db[q].y));
        }

        ulonglong2* q0 = (ulonglong2*)(&sx[1 - pb][s0][roff]);
        ulonglong2* q1 = (ulonglong2*)(&sx[1 - pb][s0 + 1][roff]);
#pragma unroll
        for (int q = 0; q < 4; ++q) {
            q0[q] = make_ulonglong2(acc0[2 * q], acc0[2 * q + 1]);
            q1[q] = make_ulonglong2(acc1[2 * q], acc1[2 * q + 1]);
        }
        __syncthreads();
        pb = 1 - pb;
    }
#pragma unroll
    for (int r = 0; r < 16; ++r)
        *(float2*)(&g_localEnd[((size_t)c * BB + b0 + roff + r) * SS + s0]) =
            make_float2(sx[pb][s0][roff + r], sx[pb][s0 + 1][roff + r]);
}

// ---------------- pass2: boundary recurrence ----------------
__global__ void __launch_bounds__(128) k_pass2(const float* __restrict__ x0) {
    const int b0 = blockIdx.x * 2;   // 32 CTAs
    const int s0 = 2 * threadIdx.x;
    __shared__ __align__(8) float sxp[SS][2];   // [k][row]

    float2 vA = *(const float2*)(&x0[(size_t)b0 * SS + s0]);
    float2 vB = *(const float2*)(&x0[(size_t)(b0 + 1) * SS + s0]);
    sxp[s0][0] = vA.x;     sxp[s0][1] = vB.x;
    sxp[s0 + 1][0] = vA.y; sxp[s0 + 1][1] = vB.y;
    *(float2*)(&g_xstart[((size_t)b0) * SS + s0])       = vA;
    *(float2*)(&g_xstart[((size_t)(b0 + 1)) * SS + s0]) = vB;
    __syncthreads();

#pragma unroll 1
    for (int c = 1; c < CCH; ++c) {
        float2 eA = *(const float2*)(&g_localEnd[((size_t)(c - 1) * BB + b0) * SS + s0]);
        float2 eB = *(const float2*)(&g_localEnd[((size_t)(c - 1) * BB + b0 + 1) * SS + s0]);
        unsigned long long acc0[4], acc1[4];
#pragma unroll
        for (int u = 0; u < 4; ++u) { acc0[u] = 0ull; acc1[u] = 0ull; }
        const float* wp = g_PA + s0;   // (A^T)^32
#pragma unroll 2
        for (int k = 0; k < SS; k += 4) {
#pragma unroll
            for (int u = 0; u < 4; ++u) {
                float2 w = *(const float2*)(wp + (size_t)(k + u) * SS);
                unsigned long long xp = *(const unsigned long long*)(&sxp[k + u][0]);
                fma2(acc0[u], xp, pack2(w.x, w.x));
                fma2(acc1[u], xp, pack2(w.y, w.y));
            }
        }
        add2(acc0[0], acc0[1]); add2(acc0[2], acc0[3]); add2(acc0[0], acc0[2]);
        add2(acc1[0], acc1[1]); add2(acc1[2], acc1[3]); add2(acc1[0], acc1[2]);
        float2 f0 = unpack2(acc0[0]);
        float2 f1 = unpack2(acc1[0]);
        f0.x += eA.x; f0.y += eB.x;
        f1.x += eA.y; f1.y += eB.y;
        __syncthreads();
        sxp[s0][0] = f0.x;     sxp[s0][1] = f0.y;
        sxp[s0 + 1][0] = f1.x; sxp[s0 + 1][1] = f1.y;
        __syncthreads();
        *(float2*)(&g_xstart[((size_t)c * BB + b0) * SS + s0])     = make_float2(f0.x, f1.x);
        *(float2*)(&g_xstart[((size_t)c * BB + b0 + 1) * SS + s0]) = make_float2(f0.y, f1.y);
    }
}

// ---------------- pass3 ----------------
__global__ void __launch_bounds__(256) k_pass3(float* __restrict__ out, int dup) {
    const int c    = blockIdx.x / NBT;
    const int b0   = (blockIdx.x % NBT) * BT;
    const int tid  = threadIdx.x;
    const int h    = tid >> 7;
    const int lane = tid & 127;
    const int s0   = 2 * lane;
    const int roff = h * 16;
    __shared__ __align__(16) float sx[2][SS][PAD];

#pragma unroll
    for (int r = 0; r < 16; ++r) {
        float2 v = *(const float2*)(&g_xstart[((size_t)c * BB + b0 + roff + r) * SS + s0]);
        sx[0][s0][roff + r]     = v.x;
        sx[0][s0 + 1][roff + r] = v.y;
    }
    __syncthreads();

    float* out2 = out + (size_t)TBS;
    int pb = 0;

#pragma unroll 1
    for (int j = 0; j < LCH; ++j) {
        const int t = c * LCH + j;

        // PREFETCH drive before the gemm (same as pass1)
        const float* dr = g_drive + ((size_t)t * BB + b0 + roff) * SS + s0;
        float2 da[8], db[8];
#pragma unroll
        for (int q = 0; q < 8; ++q) {
            da[q] = *(const float2*)(dr + (size_t)(2 * q) * SS);
            db[q] = *(const float2*)(dr + (size_t)(2 * q + 1) * SS);
        }

        unsigned long long acc0[8], acc1[8];
#pragma unroll
        for (int p = 0; p < 8; ++p) { acc0[p] = 0ull; acc1[p] = 0ull; }

        gemm_half<SS / 8>(sx[pb], roff, g_At + s0, acc0, acc1);

#pragma unroll
        for (int q = 0; q < 8; ++q) {
            add2(acc0[q], pack2(da[q].x, db[q].x));
            add2(acc1[q], pack2(da[q].y, db[q].y));
        }

        ulonglong2* q0 = (ulonglong2*)(&sx[1 - pb][s0][roff]);
        ulonglong2* q1 = (ulonglong2*)(&sx[1 - pb][s0 + 1][roff]);
#pragma unroll
        for (int q = 0; q < 4; ++q) {
            q0[q] = make_ulonglong2(acc0[2 * q], acc0[2 * q + 1]);
            q1[q] = make_ulonglong2(acc1[2 * q], acc1[2 * q + 1]);
        }

        size_t obase = ((size_t)t * BB + b0 + roff) * SS + s0;
#pragma unroll
        for (int q = 0; q < 8; ++q) {
            float2 f0 = unpack2(acc0[q]);
            float2 f1 = unpack2(acc1[q]);
            float2 oA = make_float2(f0.x, f1.x);
            float2 oB = make_float2(f0.y, f1.y);
            size_t oa = obase + (size_t)(2 * q) * SS;
            size_t ob = obase + (size_t)(2 * q + 1) * SS;
            *(float2*)(&out[oa]) = oA;
            *(float2*)(&out[ob]) = oB;
            if (dup) {
                *(float2*)(&out2[oa]) = oA;
                *(float2*)(&out2[ob]) = oB;
            }
        }
        __syncthreads();
        pb = 1 - pb;
    }
}

// ---------------- launcher ----------------
extern "C" void kernel_launch(void* const* d_in, const int* in_sizes, int n_in,
                              void* d_out, int out_size) {
    const float* x  = (const float*)d_in[0];
    const float* U  = (const float*)d_in[1];
    const float* D  = (const float*)d_in[2];
    const float* Aw = (const float*)d_in[3];
    const float* Bw = (const float*)d_in[4];
    const float* Ew = (const float*)d_in[5];
    float* out = (float*)d_out;
    int dup = (out_size >= 2 * TBS) ? 1 : 0;

    k_prep<<<(SS * SS + WK * SS + 255) / 256, 256>>>(Aw, Bw, Ew);   // 0
    k_drive<<<(TT * BB) / 32, 256>>>(U, D);                          // 1
    k_powers<<<SS / 2, 256>>>();                                     // 2
    k_pass1<<<(CCH - 1) * NBT, 256>>>();                             // 3
    k_pass2<<<BB / 2, 128>>>(x);                                     // 4
    k_pass3<<<CCH * NBT, 256>>>(out, dup);                           // 5
}